// round 15
// baseline (speedup 1.0000x reference)
#include <cuda_runtime.h>
#include <cuda_fp16.h>
#include <stdint.h>

#define Qn   2048
#define Kn   2048
#define Cin  128
#define HD   256
#define Hh   8
#define CH   32

#define SPLITK 2
#define KS     (Kn / SPLITK)   // 1024 keys per block
#define KT     32              // keys per smem tile
#define NTILES (KS / KT)       // 32
#define TQ     32              // q rows per block (2 halves x 16)

// attn per-buffer smem layout (bytes); 3-stage ring
#define KROW     528
#define VOFF     16896                  // 32*528
#define DSOFF    33792                  // VOFF + 32*528
#define DSPLANE  1152                   // floats per head plane (32q*36)
#define BUFB     70656                  // DSOFF + 8*1152*4
#define SM_BYTES (3 * BUFB)             // 211968

// proj_h smem
#define PA_PITCH 136
#define PB_PITCH 72
#define PJ_SMEM  (128 * PA_PITCH * 2 + 128 * PB_PITCH * 2)   // 53248

// out_h smem (BM=32, BN=64, kc=128, K=768)
#define OA_PITCH 136
#define OB_PITCH 72
#define OA_BYTES (32 * OA_PITCH * 2)    // 8704
#define OB_BYTES (128 * OB_PITCH * 2)   // 18432
#define OBUF     (OA_BYTES + OB_BYTES)  // 27136
#define OUT_SMEM (2 * OBUF)             // 54272

// ---------------- scratch ----------------
__device__ __align__(16) __half g_qh[Qn * HD];    // q/sqrt(32)
__device__ __align__(16) __half g_kh[Kn * HD];
__device__ __align__(16) __half g_vh[Kn * HD];
__device__ __align__(16) float  g_g[Qn * HD];     // sigmoid gate
__device__ __align__(16) float  g_pacc[SPLITK * Qn * Hh * CH];
__device__ __align__(16) float  g_pm[SPLITK * Qn * Hh];
__device__ __align__(16) float  g_pl[SPLITK * Qn * Hh];
__device__ __align__(16) __half g_w2[768 * Cin];      // [Wo_hi; Wo_lo; Wo_hi]
__device__ __align__(16) __half g_ohi[Qn * HD];       // gated out, fp16 hi
__device__ __align__(16) __half g_olo[Qn * HD];       // fp16 residual

// ---------------- asm helpers ----------------
__device__ __forceinline__ uint32_t smem_u32(const void* p) {
    return (uint32_t)__cvta_generic_to_shared(p);
}
__device__ __forceinline__ void cpasync16(uint32_t dst, const void* src) {
    asm volatile("cp.async.cg.shared.global [%0], [%1], 16;" :: "r"(dst), "l"(src));
}
__device__ __forceinline__ void cp_commit() {
    asm volatile("cp.async.commit_group;");
}
template <int N>
__device__ __forceinline__ void cp_wait() {
    asm volatile("cp.async.wait_group %0;" :: "n"(N));
}
__device__ __forceinline__ void ldsm_x2(uint32_t& r0, uint32_t& r1, uint32_t a) {
    asm volatile("ldmatrix.sync.aligned.m8n8.x2.shared.b16 {%0,%1},[%2];"
                 : "=r"(r0), "=r"(r1) : "r"(a));
}
__device__ __forceinline__ void ldsm_x2_t(uint32_t& r0, uint32_t& r1, uint32_t a) {
    asm volatile("ldmatrix.sync.aligned.m8n8.x2.trans.shared.b16 {%0,%1},[%2];"
                 : "=r"(r0), "=r"(r1) : "r"(a));
}
__device__ __forceinline__ void ldsm_x4(uint32_t* r, uint32_t a) {
    asm volatile("ldmatrix.sync.aligned.m8n8.x4.shared.b16 {%0,%1,%2,%3},[%4];"
                 : "=r"(r[0]), "=r"(r[1]), "=r"(r[2]), "=r"(r[3]) : "r"(a));
}
__device__ __forceinline__ void mma_f16(float* c, const uint32_t* a, uint32_t b0, uint32_t b1) {
    asm volatile("mma.sync.aligned.m16n8k16.row.col.f32.f16.f16.f32 "
                 "{%0,%1,%2,%3},{%4,%5,%6,%7},{%8,%9},{%0,%1,%2,%3};"
                 : "+f"(c[0]), "+f"(c[1]), "+f"(c[2]), "+f"(c[3])
                 : "r"(a[0]), "r"(a[1]), "r"(a[2]), "r"(a[3]), "r"(b0), "r"(b1));
}
__device__ __forceinline__ uint32_t pkhf(float lo, float hi) {
    __half2 h = __floats2half2_rn(lo, hi);
    return *reinterpret_cast<uint32_t*>(&h);
}

// ---------------- kernel 0: Wo hi/lo split only ---------------------------------------
__global__ __launch_bounds__(256) void convert_kernel(const float* __restrict__ Wo) {
    const int n4 = HD * Cin / 4;
    for (int i = blockIdx.x * blockDim.x + threadIdx.x; i < n4;
         i += gridDim.x * blockDim.x) {
        float4 v = ((const float4*)Wo)[i];
        __half2 h0 = __floats2half2_rn(v.x, v.y);
        __half2 h1 = __floats2half2_rn(v.z, v.w);
        __half2 l0 = __floats2half2_rn(v.x - __half2float(h0.x),
                                       v.y - __half2float(h0.y));
        __half2 l1 = __floats2half2_rn(v.z - __half2float(h1.x),
                                       v.w - __half2float(h1.y));
        int e = 4 * i;
        int row = e >> 7, col = e & 127;
        __half* b0 = g_w2 + (size_t)row * Cin + col;            // hi
        *(__half2*)b0 = h0;            *(__half2*)(b0 + 2) = h1;
        __half* b1 = b0 + 256 * Cin;                            // lo
        *(__half2*)b1 = l0;            *(__half2*)(b1 + 2) = l1;
        __half* b2 = b0 + 512 * Cin;                            // hi again
        *(__half2*)b2 = h0;            *(__half2*)(b2 + 2) = h1;
    }
}

// ---------------- kernel 1: projections via HMMA (fp32 sources, fused convert) --------
__global__ __launch_bounds__(256) void proj_h(const float* __restrict__ qx,
                                              const float* __restrict__ kvx,
                                              const float* __restrict__ Wq,
                                              const float* __restrict__ Wk,
                                              const float* __restrict__ Wv,
                                              const float* __restrict__ Wg,
                                              const float* __restrict__ bg) {
    extern __shared__ char sm[];
    __half* As = (__half*)sm;
    __half* Bs = (__half*)(sm + 128 * PA_PITCH * 2);
    const int tid = threadIdx.x, w = tid >> 5, lane = tid & 31;
    const int bm = blockIdx.x, bn = blockIdx.y, z = blockIdx.z;
    const float* A32 = (z == 0 || z == 3) ? qx : kvx;
    const float* B32 = (z == 0) ? Wq : (z == 1) ? Wk : (z == 2) ? Wv : Wg;

    // stage A [128 rows][128 cols] fp32 -> fp16
#pragma unroll
    for (int r = 0; r < 16; r++) {
        int idx = tid + 256 * r;
        int row = idx >> 5, c = idx & 31;          // c in float4 units
        float4 v = *(const float4*)(A32 + (size_t)(bm * 128 + row) * Cin + c * 4);
        __half2 h0 = __floats2half2_rn(v.x, v.y);
        __half2 h1 = __floats2half2_rn(v.z, v.w);
        uint2 p = make_uint2(*(uint32_t*)&h0, *(uint32_t*)&h1);
        *(uint2*)(As + row * PA_PITCH + c * 4) = p;
    }
    // stage B [128 K-rows][64-col slice] fp32 -> fp16
#pragma unroll
    for (int r = 0; r < 8; r++) {
        int idx = tid + 256 * r;
        int row = idx >> 4, c = idx & 15;
        float4 v = *(const float4*)(B32 + (size_t)row * HD + bn * 64 + c * 4);
        __half2 h0 = __floats2half2_rn(v.x, v.y);
        __half2 h1 = __floats2half2_rn(v.z, v.w);
        uint2 p = make_uint2(*(uint32_t*)&h0, *(uint32_t*)&h1);
        *(uint2*)(Bs + row * PB_PITCH + c * 4) = p;
    }
    __syncthreads();

    const uint32_t Ab = smem_u32(As) +
        (((16 * w + ((lane >> 3) & 1) * 8 + (lane & 7)) * PA_PITCH) + ((lane >> 4) & 1) * 8) * 2;
    const uint32_t Bb = smem_u32(Bs) + ((lane & 15) * PB_PITCH) * 2;

    float c[8][4];
#pragma unroll
    for (int n = 0; n < 8; n++)
#pragma unroll
        for (int j = 0; j < 4; j++) c[n][j] = 0.f;

#pragma unroll
    for (int ks = 0; ks < 8; ks++) {
        uint32_t a[4];
        ldsm_x4(a, Ab + ks * 32);
#pragma unroll
        for (int nf = 0; nf < 8; nf++) {
            uint32_t b0, b1;
            ldsm_x2_t(b0, b1, Bb + (ks * 16 * PB_PITCH + nf * 8) * 2);
            mma_f16(c[nf], a, b0, b1);
        }
    }

    const int rq = lane >> 2, c2 = (lane & 3) * 2;
    const int row = bm * 128 + 16 * w + rq;
    if (z == 3) {
#pragma unroll
        for (int nf = 0; nf < 8; nf++) {
            int col = bn * 64 + nf * 8 + c2;
            float b0 = bg[col], b1 = bg[col + 1];
            *(float2*)(g_g + (size_t)row * HD + col) = make_float2(
                1.f / (1.f + __expf(-(c[nf][0] + b0))),
                1.f / (1.f + __expf(-(c[nf][1] + b1))));
            *(float2*)(g_g + (size_t)(row + 8) * HD + col) = make_float2(
                1.f / (1.f + __expf(-(c[nf][2] + b0))),
                1.f / (1.f + __expf(-(c[nf][3] + b1))));
        }
    } else {
        __half* dst = (z == 0) ? g_qh : (z == 1) ? g_kh : g_vh;
        const float sc = (z == 0) ? 0.17677669529663689f : 1.f;
#pragma unroll
        for (int nf = 0; nf < 8; nf++) {
            int col = bn * 64 + nf * 8 + c2;
            *(__half2*)(dst + (size_t)row * HD + col) =
                __floats2half2_rn(c[nf][0] * sc, c[nf][1] * sc);
            *(__half2*)(dst + (size_t)(row + 8) * HD + col) =
                __floats2half2_rn(c[nf][2] * sc, c[nf][3] * sc);
        }
    }
}

// ---------------- kernel 2: flash attention (HMMA fp16, 3-stage ring, 1 bar/tile) -----
__global__ __launch_bounds__(512, 1) void attn_kernel(const float* __restrict__ bias,
                                                      const float* __restrict__ dist) {
    extern __shared__ char smem[];
    const int tid  = threadIdx.x;
    const int wid  = tid >> 5;
    const int w    = wid & 7;        // head
    const int qh   = wid >> 3;       // q-half (0/1)
    const int lane = tid & 31;
    const int q0   = blockIdx.x * TQ;
    const int sp   = blockIdx.y;
    const int kb0  = sp * KS;
    const int rq   = lane >> 2;
    const int c2   = (lane & 3) * 2;

    const uint32_t sb = smem_u32(smem);

    // Q A-fragments (2 k-steps over CH=32)
    uint32_t qa[2][4];
    {
        const __half* qp = g_qh + (size_t)(q0 + qh * 16 + rq) * HD + w * CH + c2;
#pragma unroll
        for (int s = 0; s < 2; s++) {
            qa[s][0] = *(const uint32_t*)(qp + s * 16);
            qa[s][1] = *(const uint32_t*)(qp + 8 * HD + s * 16);
            qa[s][2] = *(const uint32_t*)(qp + s * 16 + 8);
            qa[s][3] = *(const uint32_t*)(qp + 8 * HD + s * 16 + 8);
        }
    }

    float o[4][4];
#pragma unroll
    for (int n = 0; n < 4; n++)
#pragma unroll
        for (int j = 0; j < 4; j++) o[n][j] = 0.f;
    const float NINF = -__int_as_float(0x7f800000);
    float m0 = NINF, m1 = NINF, l0 = 0.f, l1 = 0.f;

    float4 dreg[4];
    float  breg[4];

    // ---- prologue: cp tile 0 into buf 0, dist(0) into regs ----
    {
        const int kb = kb0;
#pragma unroll
        for (int r = 0; r < 2; r++) {
            int idx = tid + 512 * r;
            int row = idx >> 5, c = idx & 31;
            cpasync16(sb + row * KROW + c * 16, g_kh + (size_t)(kb + row) * HD + c * 8);
            cpasync16(sb + VOFF + row * KROW + c * 16, g_vh + (size_t)(kb + row) * HD + c * 8);
        }
        cp_commit();
#pragma unroll
        for (int r = 0; r < 4; r++) {
            int idx = tid + 512 * r;
            int h4 = (idx & 1) * 4, k = (idx >> 1) & 31, q = idx >> 6;
            dreg[r] = *(const float4*)(dist + ((size_t)(q0 + q) * Kn + kb + k) * Hh + h4);
            breg[r] = __ldg(bias + (size_t)(q0 + q) * Kn + kb + k);
        }
    }

    int bi = 0;   // ring buffer index = t mod 3
    for (int t = 0; t < NTILES; t++) {
        const uint32_t bufb = sb + bi * BUFB;
        float* dsb = (float*)(smem + bi * BUFB + DSOFF);

        // store dist(t)+bias into ds[bi]
#pragma unroll
        for (int r = 0; r < 4; r++) {
            int idx = tid + 512 * r;
            int h4 = (idx & 1) * 4, k = (idx >> 1) & 31, q = idx >> 6;
            float* dp = dsb + h4 * DSPLANE + q * 36 + k;
            float bb = breg[r];
            dp[0]           = dreg[r].x + bb;
            dp[DSPLANE]     = dreg[r].y + bb;
            dp[2 * DSPLANE] = dreg[r].z + bb;
            dp[3 * DSPLANE] = dreg[r].w + bb;
        }

        if (t + 1 < NTILES) {
            const int kb = kb0 + (t + 1) * KT;
            int nbi = bi + 1; if (nbi == 3) nbi = 0;
            const uint32_t nb = sb + nbi * BUFB;
#pragma unroll
            for (int r = 0; r < 2; r++) {
                int idx = tid + 512 * r;
                int row = idx >> 5, c = idx & 31;
                cpasync16(nb + row * KROW + c * 16, g_kh + (size_t)(kb + row) * HD + c * 8);
                cpasync16(nb + VOFF + row * KROW + c * 16, g_vh + (size_t)(kb + row) * HD + c * 8);
            }
            cp_commit();
#pragma unroll
            for (int r = 0; r < 4; r++) {
                int idx = tid + 512 * r;
                int h4 = (idx & 1) * 4, k = (idx >> 1) & 31, q = idx >> 6;
                dreg[r] = *(const float4*)(dist + ((size_t)(q0 + q) * Kn + kb + k) * Hh + h4);
                breg[r] = __ldg(bias + (size_t)(q0 + q) * Kn + kb + k);
            }
            cp_wait<1>();
        } else {
            cp_wait<0>();
        }
        __syncthreads();   // the ONLY barrier per tile (ring makes trailing sync unnecessary)

        // ---- compute tile t from buffer bi ----
        const uint32_t Kb = bufb + w * 64;
        const uint32_t Vb = bufb + VOFF + w * 64;
        float* dsw = dsb + w * DSPLANE + (qh * 16) * 36;

        float s[4][4];
#pragma unroll
        for (int n = 0; n < 4; n++) {
            float2 t0 = *(float2*)(dsw + rq * 36 + n * 8 + c2);
            float2 t1 = *(float2*)(dsw + (rq + 8) * 36 + n * 8 + c2);
            s[n][0] = t0.x; s[n][1] = t0.y; s[n][2] = t1.x; s[n][3] = t1.y;
        }
#pragma unroll
        for (int ks = 0; ks < 2; ks++)
#pragma unroll
            for (int n = 0; n < 4; n++) {
                uint32_t b0, b1;
                ldsm_x2(b0, b1, Kb + (n * 8 + (lane & 7)) * KROW
                                  + ((lane >> 3) & 1) * 16 + ks * 32);
                mma_f16(s[n], qa[ks], b0, b1);
            }

        // online softmax
        float mx0 = NINF, mx1 = NINF;
#pragma unroll
        for (int n = 0; n < 4; n++) {
            mx0 = fmaxf(mx0, fmaxf(s[n][0], s[n][1]));
            mx1 = fmaxf(mx1, fmaxf(s[n][2], s[n][3]));
        }
        mx0 = fmaxf(mx0, __shfl_xor_sync(0xffffffffu, mx0, 1));
        mx0 = fmaxf(mx0, __shfl_xor_sync(0xffffffffu, mx0, 2));
        mx1 = fmaxf(mx1, __shfl_xor_sync(0xffffffffu, mx1, 1));
        mx1 = fmaxf(mx1, __shfl_xor_sync(0xffffffffu, mx1, 2));
        float nm0 = fmaxf(m0, mx0), nm1 = fmaxf(m1, mx1);
        float cr0 = __expf(m0 - nm0), cr1 = __expf(m1 - nm1);
        m0 = nm0; m1 = nm1;
        l0 *= cr0; l1 *= cr1;
#pragma unroll
        for (int n = 0; n < 4; n++) {
            o[n][0] *= cr0; o[n][1] *= cr0; o[n][2] *= cr1; o[n][3] *= cr1;
        }

        // P = exp(S - m) packed into PV A-fragments
        uint32_t pa[2][4];
        float sm0 = 0.f, sm1 = 0.f;
#pragma unroll
        for (int n = 0; n < 4; n++) {
            float p0 = __expf(s[n][0] - m0), p1 = __expf(s[n][1] - m0);
            float p2 = __expf(s[n][2] - m1), p3 = __expf(s[n][3] - m1);
            sm0 += p0 + p1; sm1 += p2 + p3;
            int j = n >> 1;
            if ((n & 1) == 0) { pa[j][0] = pkhf(p0, p1); pa[j][1] = pkhf(p2, p3); }
            else              { pa[j][2] = pkhf(p0, p1); pa[j][3] = pkhf(p2, p3); }
        }
        l0 += sm0; l1 += sm1;

        // O += P V
#pragma unroll
        for (int j = 0; j < 2; j++)
#pragma unroll
            for (int nn = 0; nn < 4; nn++) {
                uint32_t b0, b1;
                ldsm_x2_t(b0, b1, Vb + (16 * j + (lane & 15)) * KROW + nn * 16);
                mma_f16(o[nn], pa[j], b0, b1);
            }

        bi++; if (bi == 3) bi = 0;
    }

    // reduce row sums across quad
    l0 += __shfl_xor_sync(0xffffffffu, l0, 1);
    l0 += __shfl_xor_sync(0xffffffffu, l0, 2);
    l1 += __shfl_xor_sync(0xffffffffu, l1, 1);
    l1 += __shfl_xor_sync(0xffffffffu, l1, 2);

    // store split-K partials
    const int qr = q0 + qh * 16 + rq;
    const size_t i0 = ((size_t)(sp * Qn + qr) * Hh + w) * CH;
    const size_t i1 = ((size_t)(sp * Qn + qr + 8) * Hh + w) * CH;
#pragma unroll
    for (int nn = 0; nn < 4; nn++) {
        *(float2*)(g_pacc + i0 + nn * 8 + c2) = make_float2(o[nn][0], o[nn][1]);
        *(float2*)(g_pacc + i1 + nn * 8 + c2) = make_float2(o[nn][2], o[nn][3]);
    }
    if ((lane & 3) == 0) {
        g_pm[(size_t)(sp * Qn + qr) * Hh + w] = m0;
        g_pl[(size_t)(sp * Qn + qr) * Hh + w] = l0;
        g_pm[(size_t)(sp * Qn + qr + 8) * Hh + w] = m1;
        g_pl[(size_t)(sp * Qn + qr + 8) * Hh + w] = l1;
    }
}

// ---------------- kernel 3: split-K merge, thread per (q,h,c4) ------------------------
__global__ __launch_bounds__(256) void merge_kernel() {
    const int idx = blockIdx.x * 256 + threadIdx.x;
    const int c4 = idx & 7;
    const int h  = (idx >> 3) & 7;
    const int q  = idx >> 6;
    const int ih = q * Hh + h;

    float mj[SPLITK], lj[SPLITK];
    float M = -__int_as_float(0x7f800000);
#pragma unroll
    for (int j = 0; j < SPLITK; j++) {
        mj[j] = g_pm[j * Qn * Hh + ih];
        lj[j] = g_pl[j * Qn * Hh + ih];
        M = fmaxf(M, mj[j]);
    }
    float wj[SPLITK], L = 0.f;
#pragma unroll
    for (int j = 0; j < SPLITK; j++) {
        wj[j] = __expf(mj[j] - M);
        L += wj[j] * lj[j];
    }
    const float inv = 1.f / L;

    float4 a = make_float4(0.f, 0.f, 0.f, 0.f);
#pragma unroll
    for (int j = 0; j < SPLITK; j++) {
        const float4 pj = ((const float4*)g_pacc)[(size_t)(j * Qn * Hh + ih) * 8 + c4];
        a.x += wj[j] * pj.x; a.y += wj[j] * pj.y;
        a.z += wj[j] * pj.z; a.w += wj[j] * pj.w;
    }
    const float4 g = *(const float4*)(g_g + (size_t)q * HD + h * CH + c4 * 4);
    a.x *= inv * g.x; a.y *= inv * g.y; a.z *= inv * g.z; a.w *= inv * g.w;

    __half2 h0 = __floats2half2_rn(a.x, a.y);
    __half2 h1 = __floats2half2_rn(a.z, a.w);
    __half2 lo0 = __floats2half2_rn(a.x - __half2float(h0.x),
                                    a.y - __half2float(h0.y));
    __half2 lo1 = __floats2half2_rn(a.z - __half2float(h1.x),
                                    a.w - __half2float(h1.y));
    __half* ph = g_ohi + (size_t)q * HD + h * CH + c4 * 4;
    __half* pl = g_olo + (size_t)q * HD + h * CH + c4 * 4;
    *(__half2*)ph = h0;       *(__half2*)(ph + 2) = h1;
    *(__half2*)pl = lo0;      *(__half2*)(pl + 2) = lo1;
}

// ---------------- kernel 4: output projection via HMMA (hi/lo compensated) ------------
__global__ __launch_bounds__(256) void out_h(const float* __restrict__ bo,
                                             float* __restrict__ out) {
    extern __shared__ char sm[];
    const int tid = threadIdx.x, w = tid >> 5, lane = tid & 31;
    const int bm = blockIdx.x, bn = blockIdx.y;
    const int wm = w & 1, wn = w >> 1;
    const uint32_t sb = smem_u32(sm);

    auto stage = [&](int t, int buf) {
        const __half* arr = (t < 4) ? g_ohi : g_olo;
        const int colbase = (t & 1) * 128;
        const uint32_t ab = sb + buf * OBUF;
        const uint32_t bb = ab + OA_BYTES;
#pragma unroll
        for (int r = 0; r < 2; r++) {
            int idx = tid + 256 * r;
            int row = idx >> 4, c = idx & 15;
            cpasync16(ab + (row * OA_PITCH + c * 8) * 2,
                      arr + (size_t)(bm * 32 + row) * HD + colbase + c * 8);
        }
#pragma unroll
        for (int r = 0; r < 4; r++) {
            int idx = tid + 256 * r;
            int row = idx >> 3, c = idx & 7;
            cpasync16(bb + (row * OB_PITCH + c * 8) * 2,
                      g_w2 + (size_t)(t * 128 + row) * Cin + bn * 64 + c * 8);
        }
        cp_commit();
    };

    float c[2][4];
#pragma unroll
    for (int n = 0; n < 2; n++)
#pragma unroll
        for (int j = 0; j < 4; j++) c[n][j] = 0.f;

    stage(0, 0);
    for (int t = 0; t < 6; t++) {
        const int b = t & 1;
        if (t + 1 < 6) { stage(t + 1, b ^ 1); cp_wait<1>(); }
        else           { cp_wait<0>(); }
        __syncthreads();

        const uint32_t ab = sb + b * OBUF;
        const uint32_t bb = ab + OA_BYTES;
        const uint32_t Ab = ab +
            (((16 * wm + ((lane >> 3) & 1) * 8 + (lane & 7)) * OA_PITCH) + ((lane >> 4) & 1) * 8) * 2;
        const uint32_t Bb = bb + ((lane & 15) * OB_PITCH + wn * 16) * 2;

#pragma unroll
        for (int ks = 0; ks < 8; ks++) {
            uint32_t a[4];
            ldsm_x4(a, Ab + ks * 32);
#pragma unroll
            for (int nf = 0; nf < 2; nf++) {
                uint32_t b0, b1;
                ldsm_x2_t(b0, b1, Bb + (ks * 16 * OB_PITCH + nf * 8) * 2);
                mma_f16(c[nf], a, b0, b1);
            }
        }
        __syncthreads();
    }

    const int rq = lane >> 2, c2 = (lane & 3) * 2;
    const int row = bm * 32 + 16 * wm + rq;
#pragma unroll
    for (int nf = 0; nf < 2; nf++) {
        int col = bn * 64 + wn * 16 + nf * 8 + c2;
        float b0 = bo[col], b1 = bo[col + 1];
        *(float2*)(out + (size_t)row * Cin + col) =
            make_float2(c[nf][0] + b0, c[nf][1] + b1);
        *(float2*)(out + (size_t)(row + 8) * Cin + col) =
            make_float2(c[nf][2] + b0, c[nf][3] + b1);
    }
}

// ---------------- launch --------------------------------------------------------------
extern "C" void kernel_launch(void* const* d_in, const int* in_sizes, int n_in,
                              void* d_out, int out_size) {
    (void)in_sizes; (void)n_in; (void)out_size;
    const float* qx   = (const float*)d_in[0];
    const float* kvx  = (const float*)d_in[1];
    const float* bias = (const float*)d_in[2];
    const float* dist = (const float*)d_in[3];
    const float* Wq   = (const float*)d_in[4];
    const float* Wk   = (const float*)d_in[5];
    const float* Wv   = (const float*)d_in[6];
    const float* Wg   = (const float*)d_in[7];
    const float* bg   = (const float*)d_in[8];
    const float* Wo   = (const float*)d_in[9];
    const float* bo   = (const float*)d_in[10];
    float* out = (float*)d_out;

    cudaFuncSetAttribute(attn_kernel, cudaFuncAttributeMaxDynamicSharedMemorySize, SM_BYTES);
    cudaFuncSetAttribute(proj_h,      cudaFuncAttributeMaxDynamicSharedMemorySize, PJ_SMEM);
    cudaFuncSetAttribute(out_h,       cudaFuncAttributeMaxDynamicSharedMemorySize, OUT_SMEM);

    convert_kernel<<<32, 256>>>(Wo);
    proj_h<<<dim3(Qn / 128, HD / 64, 4), 256, PJ_SMEM>>>(qx, kvx, Wq, Wk, Wv, Wg, bg);
    attn_kernel<<<dim3(Qn / TQ, SPLITK), 512, SM_BYTES>>>(bias, dist);
    merge_kernel<<<dim3(Qn * Hh * 8 / 256), 256>>>();
    out_h<<<dim3(Qn / 32, Cin / 64), 256, OUT_SMEM>>>(bo, out);
}

// round 17
// speedup vs baseline: 1.1689x; 1.1689x over previous
#include <cuda_runtime.h>
#include <cuda_fp16.h>
#include <stdint.h>

#define Qn   2048
#define Kn   2048
#define Cin  128
#define HD   256
#define Hh   8
#define CH   32

#define SPLITK 2
#define KS     (Kn / SPLITK)   // 1024 keys per block
#define KT     32              // keys per smem tile
#define NTILES (KS / KT)       // 32
#define TQ     32              // q rows per block (2 halves x 16)

// attn per-buffer smem layout (bytes); 2-stage double buffer (R14 config)
#define KROW     528
#define VOFF     16896                  // 32*528
#define DSOFF    33792                  // VOFF + 32*528
#define DSPLANE  1152                   // floats per head plane (32q*36)
#define BUFB     70656                  // DSOFF + 8*1152*4
#define SM_BYTES (2 * BUFB)             // 141312

// proj_h smem
#define PA_PITCH 136
#define PB_PITCH 72
#define PJ_SMEM  (128 * PA_PITCH * 2 + 128 * PB_PITCH * 2)   // 53248

// out_h smem (BM=32, BN=64, kc=128, K=768)
#define OA_PITCH 136
#define OB_PITCH 72
#define OA_BYTES (32 * OA_PITCH * 2)    // 8704
#define OB_BYTES (128 * OB_PITCH * 2)   // 18432
#define OBUF     (OA_BYTES + OB_BYTES)  // 27136
#define OUT_SMEM (2 * OBUF)             // 54272

// ---------------- scratch ----------------
__device__ __align__(16) __half g_qh[Qn * HD];    // q/sqrt(32)
__device__ __align__(16) __half g_kh[Kn * HD];
__device__ __align__(16) __half g_vh[Kn * HD];
__device__ __align__(16) float  g_g[Qn * HD];     // sigmoid gate
__device__ __align__(16) float  g_pacc[SPLITK * Qn * Hh * CH];
__device__ __align__(16) float  g_pm[SPLITK * Qn * Hh];
__device__ __align__(16) float  g_pl[SPLITK * Qn * Hh];
__device__ __align__(16) __half g_w2[768 * Cin];      // [Wo_hi; Wo_lo; Wo_hi]
__device__ __align__(16) __half g_ohi[Qn * HD];       // gated out, fp16 hi
__device__ __align__(16) __half g_olo[Qn * HD];       // fp16 residual

// ---------------- asm helpers ----------------
__device__ __forceinline__ uint32_t smem_u32(const void* p) {
    return (uint32_t)__cvta_generic_to_shared(p);
}
__device__ __forceinline__ void cpasync16(uint32_t dst, const void* src) {
    asm volatile("cp.async.cg.shared.global [%0], [%1], 16;" :: "r"(dst), "l"(src));
}
__device__ __forceinline__ void cp_commit() {
    asm volatile("cp.async.commit_group;");
}
template <int N>
__device__ __forceinline__ void cp_wait() {
    asm volatile("cp.async.wait_group %0;" :: "n"(N));
}
__device__ __forceinline__ void ldsm_x2(uint32_t& r0, uint32_t& r1, uint32_t a) {
    asm volatile("ldmatrix.sync.aligned.m8n8.x2.shared.b16 {%0,%1},[%2];"
                 : "=r"(r0), "=r"(r1) : "r"(a));
}
__device__ __forceinline__ void ldsm_x2_t(uint32_t& r0, uint32_t& r1, uint32_t a) {
    asm volatile("ldmatrix.sync.aligned.m8n8.x2.trans.shared.b16 {%0,%1},[%2];"
                 : "=r"(r0), "=r"(r1) : "r"(a));
}
__device__ __forceinline__ void ldsm_x4(uint32_t* r, uint32_t a) {
    asm volatile("ldmatrix.sync.aligned.m8n8.x4.shared.b16 {%0,%1,%2,%3},[%4];"
                 : "=r"(r[0]), "=r"(r[1]), "=r"(r[2]), "=r"(r[3]) : "r"(a));
}
__device__ __forceinline__ void mma_f16(float* c, const uint32_t* a, uint32_t b0, uint32_t b1) {
    asm volatile("mma.sync.aligned.m16n8k16.row.col.f32.f16.f16.f32 "
                 "{%0,%1,%2,%3},{%4,%5,%6,%7},{%8,%9},{%0,%1,%2,%3};"
                 : "+f"(c[0]), "+f"(c[1]), "+f"(c[2]), "+f"(c[3])
                 : "r"(a[0]), "r"(a[1]), "r"(a[2]), "r"(a[3]), "r"(b0), "r"(b1));
}
__device__ __forceinline__ uint32_t pkhf(float lo, float hi) {
    __half2 h = __floats2half2_rn(lo, hi);
    return *reinterpret_cast<uint32_t*>(&h);
}

// ---------------- kernel 0: Wo hi/lo split only ---------------------------------------
__global__ __launch_bounds__(256) void convert_kernel(const float* __restrict__ Wo) {
    const int n4 = HD * Cin / 4;
    for (int i = blockIdx.x * blockDim.x + threadIdx.x; i < n4;
         i += gridDim.x * blockDim.x) {
        float4 v = ((const float4*)Wo)[i];
        __half2 h0 = __floats2half2_rn(v.x, v.y);
        __half2 h1 = __floats2half2_rn(v.z, v.w);
        __half2 l0 = __floats2half2_rn(v.x - __half2float(h0.x),
                                       v.y - __half2float(h0.y));
        __half2 l1 = __floats2half2_rn(v.z - __half2float(h1.x),
                                       v.w - __half2float(h1.y));
        int e = 4 * i;
        int row = e >> 7, col = e & 127;
        __half* b0 = g_w2 + (size_t)row * Cin + col;            // hi
        *(__half2*)b0 = h0;            *(__half2*)(b0 + 2) = h1;
        __half* b1 = b0 + 256 * Cin;                            // lo
        *(__half2*)b1 = l0;            *(__half2*)(b1 + 2) = l1;
        __half* b2 = b0 + 512 * Cin;                            // hi again
        *(__half2*)b2 = h0;            *(__half2*)(b2 + 2) = h1;
    }
}

// ---------------- kernel 1: projections via HMMA (fp32 sources, fused convert) --------
__global__ __launch_bounds__(256) void proj_h(const float* __restrict__ qx,
                                              const float* __restrict__ kvx,
                                              const float* __restrict__ Wq,
                                              const float* __restrict__ Wk,
                                              const float* __restrict__ Wv,
                                              const float* __restrict__ Wg,
                                              const float* __restrict__ bg) {
    extern __shared__ char sm[];
    __half* As = (__half*)sm;
    __half* Bs = (__half*)(sm + 128 * PA_PITCH * 2);
    const int tid = threadIdx.x, w = tid >> 5, lane = tid & 31;
    const int bm = blockIdx.x, bn = blockIdx.y, z = blockIdx.z;
    const float* A32 = (z == 0 || z == 3) ? qx : kvx;
    const float* B32 = (z == 0) ? Wq : (z == 1) ? Wk : (z == 2) ? Wv : Wg;

    // stage A [128 rows][128 cols] fp32 -> fp16
#pragma unroll
    for (int r = 0; r < 16; r++) {
        int idx = tid + 256 * r;
        int row = idx >> 5, c = idx & 31;          // c in float4 units
        float4 v = *(const float4*)(A32 + (size_t)(bm * 128 + row) * Cin + c * 4);
        __half2 h0 = __floats2half2_rn(v.x, v.y);
        __half2 h1 = __floats2half2_rn(v.z, v.w);
        uint2 p = make_uint2(*(uint32_t*)&h0, *(uint32_t*)&h1);
        *(uint2*)(As + row * PA_PITCH + c * 4) = p;
    }
    // stage B [128 K-rows][64-col slice] fp32 -> fp16
#pragma unroll
    for (int r = 0; r < 8; r++) {
        int idx = tid + 256 * r;
        int row = idx >> 4, c = idx & 15;
        float4 v = *(const float4*)(B32 + (size_t)row * HD + bn * 64 + c * 4);
        __half2 h0 = __floats2half2_rn(v.x, v.y);
        __half2 h1 = __floats2half2_rn(v.z, v.w);
        uint2 p = make_uint2(*(uint32_t*)&h0, *(uint32_t*)&h1);
        *(uint2*)(Bs + row * PB_PITCH + c * 4) = p;
    }
    __syncthreads();

    const uint32_t Ab = smem_u32(As) +
        (((16 * w + ((lane >> 3) & 1) * 8 + (lane & 7)) * PA_PITCH) + ((lane >> 4) & 1) * 8) * 2;
    const uint32_t Bb = smem_u32(Bs) + ((lane & 15) * PB_PITCH) * 2;

    float c[8][4];
#pragma unroll
    for (int n = 0; n < 8; n++)
#pragma unroll
        for (int j = 0; j < 4; j++) c[n][j] = 0.f;

#pragma unroll
    for (int ks = 0; ks < 8; ks++) {
        uint32_t a[4];
        ldsm_x4(a, Ab + ks * 32);
#pragma unroll
        for (int nf = 0; nf < 8; nf++) {
            uint32_t b0, b1;
            ldsm_x2_t(b0, b1, Bb + (ks * 16 * PB_PITCH + nf * 8) * 2);
            mma_f16(c[nf], a, b0, b1);
        }
    }

    const int rq = lane >> 2, c2 = (lane & 3) * 2;
    const int row = bm * 128 + 16 * w + rq;
    if (z == 3) {
#pragma unroll
        for (int nf = 0; nf < 8; nf++) {
            int col = bn * 64 + nf * 8 + c2;
            float b0 = bg[col], b1 = bg[col + 1];
            *(float2*)(g_g + (size_t)row * HD + col) = make_float2(
                1.f / (1.f + __expf(-(c[nf][0] + b0))),
                1.f / (1.f + __expf(-(c[nf][1] + b1))));
            *(float2*)(g_g + (size_t)(row + 8) * HD + col) = make_float2(
                1.f / (1.f + __expf(-(c[nf][2] + b0))),
                1.f / (1.f + __expf(-(c[nf][3] + b1))));
        }
    } else {
        __half* dst = (z == 0) ? g_qh : (z == 1) ? g_kh : g_vh;
        const float sc = (z == 0) ? 0.17677669529663689f : 1.f;
#pragma unroll
        for (int nf = 0; nf < 8; nf++) {
            int col = bn * 64 + nf * 8 + c2;
            *(__half2*)(dst + (size_t)row * HD + col) =
                __floats2half2_rn(c[nf][0] * sc, c[nf][1] * sc);
            *(__half2*)(dst + (size_t)(row + 8) * HD + col) =
                __floats2half2_rn(c[nf][2] * sc, c[nf][3] * sc);
        }
    }
}

// ---------------- kernel 2: flash attention (HMMA fp16, 512 thr, TQ=32, R14 exact) ----
__global__ __launch_bounds__(512, 1) void attn_kernel(const float* __restrict__ bias,
                                                      const float* __restrict__ dist) {
    extern __shared__ char smem[];
    const int tid  = threadIdx.x;
    const int wid  = tid >> 5;
    const int w    = wid & 7;        // head
    const int qh   = wid >> 3;       // q-half (0/1)
    const int lane = tid & 31;
    const int q0   = blockIdx.x * TQ;
    const int sp   = blockIdx.y;
    const int kb0  = sp * KS;
    const int rq   = lane >> 2;
    const int c2   = (lane & 3) * 2;

    const uint32_t sb = smem_u32(smem);

    // Q A-fragments (2 k-steps over CH=32)
    uint32_t qa[2][4];
    {
        const __half* qp = g_qh + (size_t)(q0 + qh * 16 + rq) * HD + w * CH + c2;
#pragma unroll
        for (int s = 0; s < 2; s++) {
            qa[s][0] = *(const uint32_t*)(qp + s * 16);
            qa[s][1] = *(const uint32_t*)(qp + 8 * HD + s * 16);
            qa[s][2] = *(const uint32_t*)(qp + s * 16 + 8);
            qa[s][3] = *(const uint32_t*)(qp + 8 * HD + s * 16 + 8);
        }
    }

    float o[4][4];
#pragma unroll
    for (int n = 0; n < 4; n++)
#pragma unroll
        for (int j = 0; j < 4; j++) o[n][j] = 0.f;
    const float NINF = -__int_as_float(0x7f800000);
    float m0 = NINF, m1 = NINF, l0 = 0.f, l1 = 0.f;

    float4 dreg[4];
    float  breg[4];

    // ---- prologue: start tile 0 ----
    {
        const int kb = kb0;
#pragma unroll
        for (int r = 0; r < 2; r++) {
            int idx = tid + 512 * r;
            int row = idx >> 5, c = idx & 31;
            cpasync16(sb + row * KROW + c * 16, g_kh + (size_t)(kb + row) * HD + c * 8);
            cpasync16(sb + VOFF + row * KROW + c * 16, g_vh + (size_t)(kb + row) * HD + c * 8);
        }
        cp_commit();
#pragma unroll
        for (int r = 0; r < 4; r++) {
            int idx = tid + 512 * r;
            int h4 = (idx & 1) * 4, k = (idx >> 1) & 31, q = idx >> 6;   // q 0..31
            dreg[r] = *(const float4*)(dist + ((size_t)(q0 + q) * Kn + kb + k) * Hh + h4);
            breg[r] = __ldg(bias + (size_t)(q0 + q) * Kn + kb + k);
        }
    }

    for (int t = 0; t < NTILES; t++) {
        const int b = t & 1;
        const uint32_t bufb = sb + b * BUFB;
        float* dsb = (float*)(smem + b * BUFB + DSOFF);

        // store dist(t)+bias into ds[b]
#pragma unroll
        for (int r = 0; r < 4; r++) {
            int idx = tid + 512 * r;
            int h4 = (idx & 1) * 4, k = (idx >> 1) & 31, q = idx >> 6;
            float* dp = dsb + h4 * DSPLANE + q * 36 + k;
            float bb = breg[r];
            dp[0]           = dreg[r].x + bb;
            dp[DSPLANE]     = dreg[r].y + bb;
            dp[2 * DSPLANE] = dreg[r].z + bb;
            dp[3 * DSPLANE] = dreg[r].w + bb;
        }

        if (t + 1 < NTILES) {
            const int kb = kb0 + (t + 1) * KT;
            const uint32_t nb = sb + (b ^ 1) * BUFB;
#pragma unroll
            for (int r = 0; r < 2; r++) {
                int idx = tid + 512 * r;
                int row = idx >> 5, c = idx & 31;
                cpasync16(nb + row * KROW + c * 16, g_kh + (size_t)(kb + row) * HD + c * 8);
                cpasync16(nb + VOFF + row * KROW + c * 16, g_vh + (size_t)(kb + row) * HD + c * 8);
            }
            cp_commit();
#pragma unroll
            for (int r = 0; r < 4; r++) {
                int idx = tid + 512 * r;
                int h4 = (idx & 1) * 4, k = (idx >> 1) & 31, q = idx >> 6;
                dreg[r] = *(const float4*)(dist + ((size_t)(q0 + q) * Kn + kb + k) * Hh + h4);
                breg[r] = __ldg(bias + (size_t)(q0 + q) * Kn + kb + k);
            }
            cp_wait<1>();
        } else {
            cp_wait<0>();
        }
        __syncthreads();

        // ---- compute tile t from buffer b ----
        const uint32_t Kb = bufb + w * 64;
        const uint32_t Vb = bufb + VOFF + w * 64;
        float* dsw = dsb + w * DSPLANE + (qh * 16) * 36;

        float s[4][4];
#pragma unroll
        for (int n = 0; n < 4; n++) {
            float2 t0 = *(float2*)(dsw + rq * 36 + n * 8 + c2);
            float2 t1 = *(float2*)(dsw + (rq + 8) * 36 + n * 8 + c2);
            s[n][0] = t0.x; s[n][1] = t0.y; s[n][2] = t1.x; s[n][3] = t1.y;
        }
#pragma unroll
        for (int ks = 0; ks < 2; ks++)
#pragma unroll
            for (int n = 0; n < 4; n++) {
                uint32_t b0, b1;
                ldsm_x2(b0, b1, Kb + (n * 8 + (lane & 7)) * KROW
                                  + ((lane >> 3) & 1) * 16 + ks * 32);
                mma_f16(s[n], qa[ks], b0, b1);
            }

        // online softmax
        float mx0 = NINF, mx1 = NINF;
#pragma unroll
        for (int n = 0; n < 4; n++) {
            mx0 = fmaxf(mx0, fmaxf(s[n][0], s[n][1]));
            mx1 = fmaxf(mx1, fmaxf(s[n][2], s[n][3]));
        }
        mx0 = fmaxf(mx0, __shfl_xor_sync(0xffffffffu, mx0, 1));
        mx0 = fmaxf(mx0, __shfl_xor_sync(0xffffffffu, mx0, 2));
        mx1 = fmaxf(mx1, __shfl_xor_sync(0xffffffffu, mx1, 1));
        mx1 = fmaxf(mx1, __shfl_xor_sync(0xffffffffu, mx1, 2));
        float nm0 = fmaxf(m0, mx0), nm1 = fmaxf(m1, mx1);
        float cr0 = __expf(m0 - nm0), cr1 = __expf(m1 - nm1);
        m0 = nm0; m1 = nm1;
        l0 *= cr0; l1 *= cr1;
#pragma unroll
        for (int n = 0; n < 4; n++) {
            o[n][0] *= cr0; o[n][1] *= cr0; o[n][2] *= cr1; o[n][3] *= cr1;
        }

        // P = exp(S - m) packed into PV A-fragments
        uint32_t pa[2][4];
        float sm0 = 0.f, sm1 = 0.f;
#pragma unroll
        for (int n = 0; n < 4; n++) {
            float p0 = __expf(s[n][0] - m0), p1 = __expf(s[n][1] - m0);
            float p2 = __expf(s[n][2] - m1), p3 = __expf(s[n][3] - m1);
            sm0 += p0 + p1; sm1 += p2 + p3;
            int j = n >> 1;
            if ((n & 1) == 0) { pa[j][0] = pkhf(p0, p1); pa[j][1] = pkhf(p2, p3); }
            else              { pa[j][2] = pkhf(p0, p1); pa[j][3] = pkhf(p2, p3); }
        }
        l0 += sm0; l1 += sm1;

        // O += P V
#pragma unroll
        for (int j = 0; j < 2; j++)
#pragma unroll
            for (int nn = 0; nn < 4; nn++) {
                uint32_t b0, b1;
                ldsm_x2_t(b0, b1, Vb + (16 * j + (lane & 15)) * KROW + nn * 16);
                mma_f16(o[nn], pa[j], b0, b1);
            }
        __syncthreads();
    }

    // reduce row sums across quad
    l0 += __shfl_xor_sync(0xffffffffu, l0, 1);
    l0 += __shfl_xor_sync(0xffffffffu, l0, 2);
    l1 += __shfl_xor_sync(0xffffffffu, l1, 1);
    l1 += __shfl_xor_sync(0xffffffffu, l1, 2);

    // store split-K partials
    const int qr = q0 + qh * 16 + rq;
    const size_t i0 = ((size_t)(sp * Qn + qr) * Hh + w) * CH;
    const size_t i1 = ((size_t)(sp * Qn + qr + 8) * Hh + w) * CH;
#pragma unroll
    for (int nn = 0; nn < 4; nn++) {
        *(float2*)(g_pacc + i0 + nn * 8 + c2) = make_float2(o[nn][0], o[nn][1]);
        *(float2*)(g_pacc + i1 + nn * 8 + c2) = make_float2(o[nn][2], o[nn][3]);
    }
    if ((lane & 3) == 0) {
        g_pm[(size_t)(sp * Qn + qr) * Hh + w] = m0;
        g_pl[(size_t)(sp * Qn + qr) * Hh + w] = l0;
        g_pm[(size_t)(sp * Qn + qr + 8) * Hh + w] = m1;
        g_pl[(size_t)(sp * Qn + qr + 8) * Hh + w] = l1;
    }
}

// ---------------- kernel 3: split-K merge, thread per (q,h,c4) ------------------------
__global__ __launch_bounds__(256) void merge_kernel() {
    const int idx = blockIdx.x * 256 + threadIdx.x;
    const int c4 = idx & 7;
    const int h  = (idx >> 3) & 7;
    const int q  = idx >> 6;
    const int ih = q * Hh + h;

    float mj[SPLITK], lj[SPLITK];
    float M = -__int_as_float(0x7f800000);
#pragma unroll
    for (int j = 0; j < SPLITK; j++) {
        mj[j] = g_pm[j * Qn * Hh + ih];
        lj[j] = g_pl[j * Qn * Hh + ih];
        M = fmaxf(M, mj[j]);
    }
    float wj[SPLITK], L = 0.f;
#pragma unroll
    for (int j = 0; j < SPLITK; j++) {
        wj[j] = __expf(mj[j] - M);
        L += wj[j] * lj[j];
    }
    const float inv = 1.f / L;

    float4 a = make_float4(0.f, 0.f, 0.f, 0.f);
#pragma unroll
    for (int j = 0; j < SPLITK; j++) {
        const float4 pj = ((const float4*)g_pacc)[(size_t)(j * Qn * Hh + ih) * 8 + c4];
        a.x += wj[j] * pj.x; a.y += wj[j] * pj.y;
        a.z += wj[j] * pj.z; a.w += wj[j] * pj.w;
    }
    const float4 g = *(const float4*)(g_g + (size_t)q * HD + h * CH + c4 * 4);
    a.x *= inv * g.x; a.y *= inv * g.y; a.z *= inv * g.z; a.w *= inv * g.w;

    __half2 h0 = __floats2half2_rn(a.x, a.y);
    __half2 h1 = __floats2half2_rn(a.z, a.w);
    __half2 lo0 = __floats2half2_rn(a.x - __half2float(h0.x),
                                    a.y - __half2float(h0.y));
    __half2 lo1 = __floats2half2_rn(a.z - __half2float(h1.x),
                                    a.w - __half2float(h1.y));
    __half* ph = g_ohi + (size_t)q * HD + h * CH + c4 * 4;
    __half* pl = g_olo + (size_t)q * HD + h * CH + c4 * 4;
    *(__half2*)ph = h0;       *(__half2*)(ph + 2) = h1;
    *(__half2*)pl = lo0;      *(__half2*)(pl + 2) = lo1;
}

// ---------------- kernel 4: output projection via HMMA (hi/lo compensated) ------------
__global__ __launch_bounds__(256) void out_h(const float* __restrict__ bo,
                                             float* __restrict__ out) {
    extern __shared__ char sm[];
    const int tid = threadIdx.x, w = tid >> 5, lane = tid & 31;
    const int bm = blockIdx.x, bn = blockIdx.y;
    const int wm = w & 1, wn = w >> 1;
    const uint32_t sb = smem_u32(sm);

    auto stage = [&](int t, int buf) {
        const __half* arr = (t < 4) ? g_ohi : g_olo;
        const int colbase = (t & 1) * 128;
        const uint32_t ab = sb + buf * OBUF;
        const uint32_t bb = ab + OA_BYTES;
#pragma unroll
        for (int r = 0; r < 2; r++) {
            int idx = tid + 256 * r;
            int row = idx >> 4, c = idx & 15;
            cpasync16(ab + (row * OA_PITCH + c * 8) * 2,
                      arr + (size_t)(bm * 32 + row) * HD + colbase + c * 8);
        }
#pragma unroll
        for (int r = 0; r < 4; r++) {
            int idx = tid + 256 * r;
            int row = idx >> 3, c = idx & 7;
            cpasync16(bb + (row * OB_PITCH + c * 8) * 2,
                      g_w2 + (size_t)(t * 128 + row) * Cin + bn * 64 + c * 8);
        }
        cp_commit();
    };

    float c[2][4];
#pragma unroll
    for (int n = 0; n < 2; n++)
#pragma unroll
        for (int j = 0; j < 4; j++) c[n][j] = 0.f;

    stage(0, 0);
    for (int t = 0; t < 6; t++) {
        const int b = t & 1;
        if (t + 1 < 6) { stage(t + 1, b ^ 1); cp_wait<1>(); }
        else           { cp_wait<0>(); }
        __syncthreads();

        const uint32_t ab = sb + b * OBUF;
        const uint32_t bb = ab + OA_BYTES;
        const uint32_t Ab = ab +
            (((16 * wm + ((lane >> 3) & 1) * 8 + (lane & 7)) * OA_PITCH) + ((lane >> 4) & 1) * 8) * 2;
        const uint32_t Bb = bb + ((lane & 15) * OB_PITCH + wn * 16) * 2;

#pragma unroll
        for (int ks = 0; ks < 8; ks++) {
            uint32_t a[4];
            ldsm_x4(a, Ab + ks * 32);
#pragma unroll
            for (int nf = 0; nf < 2; nf++) {
                uint32_t b0, b1;
                ldsm_x2_t(b0, b1, Bb + (ks * 16 * OB_PITCH + nf * 8) * 2);
                mma_f16(c[nf], a, b0, b1);
            }
        }
        __syncthreads();
    }

    const int rq = lane >> 2, c2 = (lane & 3) * 2;
    const int row = bm * 32 + 16 * wm + rq;
#pragma unroll
    for (int nf = 0; nf < 2; nf++) {
        int col = bn * 64 + wn * 16 + nf * 8 + c2;
        float b0 = bo[col], b1 = bo[col + 1];
        *(float2*)(out + (size_t)row * Cin + col) =
            make_float2(c[nf][0] + b0, c[nf][1] + b1);
        *(float2*)(out + (size_t)(row + 8) * Cin + col) =
            make_float2(c[nf][2] + b0, c[nf][3] + b1);
    }
}

// ---------------- launch --------------------------------------------------------------
extern "C" void kernel_launch(void* const* d_in, const int* in_sizes, int n_in,
                              void* d_out, int out_size) {
    (void)in_sizes; (void)n_in; (void)out_size;
    const float* qx   = (const float*)d_in[0];
    const float* kvx  = (const float*)d_in[1];
    const float* bias = (const float*)d_in[2];
    const float* dist = (const float*)d_in[3];
    const float* Wq   = (const float*)d_in[4];
    const float* Wk   = (const float*)d_in[5];
    const float* Wv   = (const float*)d_in[6];
    const float* Wg   = (const float*)d_in[7];
    const float* bg   = (const float*)d_in[8];
    const float* Wo   = (const float*)d_in[9];
    const float* bo   = (const float*)d_in[10];
    float* out = (float*)d_out;

    cudaFuncSetAttribute(attn_kernel, cudaFuncAttributeMaxDynamicSharedMemorySize, SM_BYTES);
    cudaFuncSetAttribute(proj_h,      cudaFuncAttributeMaxDynamicSharedMemorySize, PJ_SMEM);
    cudaFuncSetAttribute(out_h,       cudaFuncAttributeMaxDynamicSharedMemorySize, OUT_SMEM);

    convert_kernel<<<32, 256>>>(Wo);
    proj_h<<<dim3(Qn / 128, HD / 64, 4), 256, PJ_SMEM>>>(qx, kvx, Wq, Wk, Wv, Wg, bg);
    attn_kernel<<<dim3(Qn / TQ, SPLITK), 512, SM_BYTES>>>(bias, dist);
    merge_kernel<<<dim3(Qn * Hh * 8 / 256), 256>>>();
    out_h<<<dim3(Qn / 32, Cin / 64), 256, OUT_SMEM>>>(bo, out);
}